// round 16
// baseline (speedup 1.0000x reference)
#include <cuda_runtime.h>
#include <cstdint>

// Problem dims (fixed by the dataset problem)
#define RB 64      // batch
#define RT 512     // time steps
#define RI 128     // input dim
#define RH 512     // hidden dim
#define RO 64      // output dim

// ---------------------------------------------------------------------------
// Device scratch (allocation-free rule: __device__ globals)
// ---------------------------------------------------------------------------
__device__ float g_winT[RI * RH];                // W_in transposed: [I][H]
__device__ float g_xproj[(size_t)RB * RT * RH];  // [B][T][H] input projections

// Packed fp32x2 helpers (Blackwell FFMA2 — ptxas never emits this from C++)
#define PK2(dst, lo, hi) \
    asm("mov.b64 %0, {%1, %2};" : "=l"(dst) : "f"(lo), "f"(hi))
#define UPK2(lo, hi, src) \
    asm("mov.b64 {%0, %1}, %2;" : "=f"(lo), "=f"(hi) : "l"(src))
#define FMA2(acc, a, b) \
    asm("fma.rn.f32x2 %0, %1, %2, %0;" : "+l"(acc) : "l"(a), "l"(b))

// ---------------------------------------------------------------------------
// Kernel 0: transpose W_in [H][I] -> g_winT [I][H]  (tiny, 256 KB)
// ---------------------------------------------------------------------------
__global__ void k0_transpose(const float* __restrict__ W_in) {
    int idx = blockIdx.x * blockDim.x + threadIdx.x;   // 0 .. I*H-1
    int h = idx & (RH - 1);
    int i = idx >> 9;           // idx / RH
    g_winT[i * RH + h] = W_in[h * RI + i];
}

// ---------------------------------------------------------------------------
// Kernel 1: x_proj[b][t][h] = sum_i inputs[b][t][i] * W_in[h][i]
// Tiled fp32 GEMM: CTA = 64 rows (b,t) x 128 h-cols, K = 128 (one pass).
// ---------------------------------------------------------------------------
#define K1_SMEM_BYTES ((64 * 128 + 128 * 132) * 4)

__global__ void k1_xproj(const float* __restrict__ inp) {
    extern __shared__ float sm[];
    float* As = sm;                  // [64][128]
    float* Ws = sm + 64 * 128;       // [128][132] (padded, k-major)
    const int row0 = blockIdx.x * 64;   // row in [B*T)
    const int hc   = blockIdx.y * 128;  // h col base
    const int tid  = threadIdx.x;

    for (int idx = tid; idx < 64 * 128; idx += 256)
        As[idx] = inp[(size_t)row0 * RI + idx];     // rows contiguous
    for (int idx = tid; idx < 128 * 128; idx += 256) {
        int i = idx >> 7, h = idx & 127;
        Ws[i * 132 + h] = g_winT[i * RH + hc + h];
    }
    __syncthreads();

    const int colg = tid & 31;     // 32 col groups (h = colg + 32*j)
    const int warp = tid >> 5;     // 8 row groups (r = warp + 8*jr)
    float acc[8][4];
#pragma unroll
    for (int a = 0; a < 8; a++)
#pragma unroll
        for (int b = 0; b < 4; b++) acc[a][b] = 0.f;

#pragma unroll 4
    for (int k = 0; k < 128; k++) {
        float w[4], a[8];
#pragma unroll
        for (int j = 0; j < 4; j++) w[j] = Ws[k * 132 + colg + 32 * j];
#pragma unroll
        for (int jr = 0; jr < 8; jr++) a[jr] = As[(warp + 8 * jr) * 128 + k];
#pragma unroll
        for (int jr = 0; jr < 8; jr++)
#pragma unroll
            for (int j = 0; j < 4; j++) acc[jr][j] += a[jr] * w[j];
    }

#pragma unroll
    for (int jr = 0; jr < 8; jr++)
#pragma unroll
        for (int j = 0; j < 4; j++)
            g_xproj[(size_t)(row0 + warp + 8 * jr) * RH + hc + colg + 32 * j] = acc[jr][j];
}

// ---------------------------------------------------------------------------
// Kernel 2: FUSED recurrent scan + output GEMM. Grid: 64 CTAs = 8 clusters
// x 8 CTAs; cluster owns 8 batch rows (groups G0/G1); CTA rank r owns hidden
// cols [64r,64r+64) AND output cols [8r,8r+8). W_rec register-resident.
//
// Per step t:
//   [all 8 warps] main GEMM G0->red0, G1->red1 (FFMA2, W in regs)
//   __syncthreads
//   [warps 0-3]  epilogue: reduce, tanh.approx, leaky update, DSMEM pushes
//   [warps 4-7]  (t>0) transpose hb[par] k-major -> hbt b-major, bar.sync,
//                out[t-1] = Wo * h(t-1): float4 pairs straight into FMA2
//                (zero packing movs), shfl khalf-reduce, STG
//   barrier.cluster (arrive ... xp prefetch ... wait)
// Post-loop: out[511] + h_final from hb[0]. No g_hhist, no k3, no k4.
// Wo + hbt live in the W-staging SMEM region (dead after wr regs load).
// ---------------------------------------------------------------------------
#define K2_WSTRIDE 72                      // floats per k-row of W staging (pad)
#define K2_WO_OFF  0                       // overlay: Wo[8][520] (after init)
#define K2_WO_STR  520
#define K2_HBT_OFF 4608                    // overlay: hbt[8][516]
#define K2_HBT_STR 516
#define K2_HB0  (512 * K2_WSTRIDE)         // 36864: hb0[2][512][4]
#define K2_HB1  (K2_HB0 + 4096)            // 40960: hb1[2][512][4]
#define K2_RED0 (K2_HB1 + 4096)            // 45056: red0[16][4][64]
#define K2_RED1 (K2_RED0 + 4096)           // 49152: red1[16][4][64]
#define K2_BS   (K2_RED1 + 4096)           // 53248: bias[64]
#define K2_SMEM_FLOATS (K2_BS + 64)        // 53312
#define K2_SMEM_BYTES (K2_SMEM_FLOATS * 4) // 213248 B

__global__ void __launch_bounds__(256, 1)
k2_rnn(const float* __restrict__ hidden,
       const float* __restrict__ W_rec,
       const float* __restrict__ bvec,
       const float* __restrict__ W_out,
       const float* __restrict__ b_out,
       float* __restrict__ out) {
    extern __shared__ float sm[];
    float* Wl   = sm;                   // [512][72]   W staging (init only)
    float* Wo   = sm + K2_WO_OFF;       // [8][520]    W_out slice (overlay)
    float* hbt  = sm + K2_HBT_OFF;      // [8][516]    b-major h (overlay)
    float* hb0  = sm + K2_HB0;          // [2][512][4] G0 h, k-major, b minor
    float* hb1  = sm + K2_HB1;          // [2][512][4] G1 h
    float* red0 = sm + K2_RED0;         // [16][4][64] G0 partials
    float* red1 = sm + K2_RED1;         // [16][4][64] G1 partials
    float* bs   = sm + K2_BS;           // [64] bias slice

    const int tid  = threadIdx.x;
    const unsigned rank = blockIdx.x & 7;     // == %cluster_ctarank for (8,1,1)
    const int b0  = (blockIdx.x >> 3) * 8;    // batch base (8 rows per cluster)
    const int c0g = rank * 64;                // hidden col base for this CTA

    // Stage W_rec slice into SMEM, transposing to k-major (one-time)
    for (int idx = tid; idx < 64 * 512; idx += 256) {
        int c = idx >> 9, k = idx & 511;
        Wl[k * K2_WSTRIDE + c] = W_rec[(size_t)(c0g + c) * RH + k];
    }
    if (tid < 64) bs[tid] = bvec[c0g + tid];
    // Initial hidden -> slot 0 of both groups (outside Wl region)
    for (int idx = tid; idx < 4096; idx += 256) {
        int half = idx >> 11;          // 0: G0, 1: G1
        int j = idx & 2047;
        int b = j & 3, k = j >> 2;
        (half ? hb1 : hb0)[k * 4 + b] = hidden[(b0 + half * 4 + b) * RH + k];
    }
    __syncthreads();

    const int colg   = tid & 15;
    const int kslice = tid >> 4;
    const int kbase  = kslice * 32;

    // ---- pull this thread's W_rec tile into registers (64 pairs) ----
    ulonglong2 wr[32];
#pragma unroll
    for (int kk = 0; kk < 32; kk++)
        wr[kk] = *reinterpret_cast<const ulonglong2*>(
            Wl + (kbase + kk) * K2_WSTRIDE + colg * 4);   // (w0,w1),(w2,w3)
    __syncthreads();   // Wl fully consumed — overlay region may be written

    // ---- load W_out slice into the overlay (8 o x 512 k) ----
    for (int idx = tid; idx < 8 * 512; idx += 256) {
        int o = idx >> 9, k = idx & 511;
        Wo[o * K2_WO_STR + k] = W_out[(size_t)(rank * 8 + o) * RH + k];
    }

    uint32_t smem_u32;
    asm("{ .reg .u64 t; cvta.to.shared.u64 t, %1; cvt.u32.u64 %0, t; }"
        : "=r"(smem_u32) : "l"(sm));
    const uint32_t hb0_base = smem_u32 + (uint32_t)(K2_HB0 * 4);
    uint32_t pb[8];      // hb0 base at each destination CTA
#pragma unroll
    for (int r = 0; r < 8; r++)
        asm("mapa.shared::cluster.u32 %0, %1, %2;" : "=r"(pb[r]) : "r"(hb0_base), "r"(r));

    // Lower epilogue (tid<128): group eg, one col x 4 batch rows
    const int eg  = (tid >> 6) & 1;
    const int uc  = tid & 63;
    const int gcu = c0g + uc;
    const float bias = bs[uc];
    const float* xp_p = g_xproj + (size_t)(b0 + 4 * eg) * RT * RH + gcu;
    const uint32_t grpoff = (uint32_t)(eg * 16384);   // hb1 is +16384 B after hb0
    const uint32_t choff  = (uint32_t)(gcu * 16);     // byte offset of col's float4
    float* myhb  = eg ? hb1 : hb0;
    const float* myred = eg ? red1 : red0;

    // Upper out-GEMM mapping (tid>=128): ut -> o, khalf, b8
    const int ut    = tid - 128;          // 0..127 (valid when tid>=128)
    const int uo    = ut & 7;             // local out col
    const int ukh   = (ut >> 3) & 1;      // k half (shfl partner = lane^8)
    const int ub8   = ut >> 4;            // batch row 0..7
    float ubo = 0.f;
    if (tid >= 128) ubo = __ldg(&b_out[rank * 8 + uo]);
    float* out_p = out + (size_t)(b0 + ub8) * RT * RO + rank * 8 + uo;

    float4* red04 = reinterpret_cast<float4*>(red0);
    float4* red14 = reinterpret_cast<float4*>(red1);

    __syncthreads();
    // Initial hb visible cluster-wide before any remote push targets us
    asm volatile("barrier.cluster.arrive.aligned;" ::: "memory");
    asm volatile("barrier.cluster.wait.aligned;"   ::: "memory");

    // Prefetch xp(0) (lower threads only)
    float xp0 = 0.f, xp1 = 0.f, xp2 = 0.f, xp3 = 0.f;
    if (tid < 128) {
        xp0 = __ldg(xp_p);
        xp1 = __ldg(xp_p + (size_t)RT * RH);
        xp2 = __ldg(xp_p + 2 * (size_t)RT * RH);
        xp3 = __ldg(xp_p + 3 * (size_t)RT * RH);
    }

    for (int t = 0; t < RT; t++) {
        const int par = t & 1;

        // ---- main GEMM G0 ----
        {
            const float4* h4 = reinterpret_cast<const float4*>(hb0 + par * 2048 + kbase * 4);
            uint64_t a0p0 = 0, a0p1 = 0, a1p0 = 0, a1p1 = 0;
            uint64_t a2p0 = 0, a2p1 = 0, a3p0 = 0, a3p1 = 0;
#pragma unroll
            for (int kk = 0; kk < 32; kk++) {
                const float4 hv = h4[kk];
                uint64_t hd0, hd1, hd2, hd3;
                PK2(hd0, hv.x, hv.x);
                PK2(hd1, hv.y, hv.y);
                PK2(hd2, hv.z, hv.z);
                PK2(hd3, hv.w, hv.w);
                FMA2(a0p0, hd0, wr[kk].x); FMA2(a0p1, hd0, wr[kk].y);
                FMA2(a1p0, hd1, wr[kk].x); FMA2(a1p1, hd1, wr[kk].y);
                FMA2(a2p0, hd2, wr[kk].x); FMA2(a2p1, hd2, wr[kk].y);
                FMA2(a3p0, hd3, wr[kk].x); FMA2(a3p1, hd3, wr[kk].y);
            }
            float4* rp = red04 + kslice * 64;
            float4 f;
            UPK2(f.x, f.y, a0p0); UPK2(f.z, f.w, a0p1); rp[0 * 16 + colg] = f;
            UPK2(f.x, f.y, a1p0); UPK2(f.z, f.w, a1p1); rp[1 * 16 + colg] = f;
            UPK2(f.x, f.y, a2p0); UPK2(f.z, f.w, a2p1); rp[2 * 16 + colg] = f;
            UPK2(f.x, f.y, a3p0); UPK2(f.z, f.w, a3p1); rp[3 * 16 + colg] = f;
        }
        // ---- main GEMM G1 ----
        {
            const float4* h4 = reinterpret_cast<const float4*>(hb1 + par * 2048 + kbase * 4);
            uint64_t a0p0 = 0, a0p1 = 0, a1p0 = 0, a1p1 = 0;
            uint64_t a2p0 = 0, a2p1 = 0, a3p0 = 0, a3p1 = 0;
#pragma unroll
            for (int kk = 0; kk < 32; kk++) {
                const float4 hv = h4[kk];
                uint64_t hd0, hd1, hd2, hd3;
                PK2(hd0, hv.x, hv.x);
                PK2(hd1, hv.y, hv.y);
                PK2(hd2, hv.z, hv.z);
                PK2(hd3, hv.w, hv.w);
                FMA2(a0p0, hd0, wr[kk].x); FMA2(a0p1, hd0, wr[kk].y);
                FMA2(a1p0, hd1, wr[kk].x); FMA2(a1p1, hd1, wr[kk].y);
                FMA2(a2p0, hd2, wr[kk].x); FMA2(a2p1, hd2, wr[kk].y);
                FMA2(a3p0, hd3, wr[kk].x); FMA2(a3p1, hd3, wr[kk].y);
            }
            float4* rp = red14 + kslice * 64;
            float4 f;
            UPK2(f.x, f.y, a0p0); UPK2(f.z, f.w, a0p1); rp[0 * 16 + colg] = f;
            UPK2(f.x, f.y, a1p0); UPK2(f.z, f.w, a1p1); rp[1 * 16 + colg] = f;
            UPK2(f.x, f.y, a2p0); UPK2(f.z, f.w, a2p1); rp[2 * 16 + colg] = f;
            UPK2(f.x, f.y, a3p0); UPK2(f.z, f.w, a3p1); rp[3 * 16 + colg] = f;
        }

        __syncthreads();   // partials visible; also protects hbt WAR (below)

        if (tid < 128) {
            // ---- lower: recurrent epilogue ----
            float s0 = 0.f, s1 = 0.f, s2 = 0.f, s3 = 0.f;
#pragma unroll
            for (int ss = 0; ss < 16; ss++) {
                const float* q = myred + ss * 256 + uc;
                s0 += q[0];
                s1 += q[64];
                s2 += q[128];
                s3 += q[192];
            }
            float t0, t1, t2, t3;
            asm("tanh.approx.f32 %0, %1;" : "=f"(t0) : "f"(s0 + xp0 + bias));
            asm("tanh.approx.f32 %0, %1;" : "=f"(t1) : "f"(s1 + xp1 + bias));
            asm("tanh.approx.f32 %0, %1;" : "=f"(t2) : "f"(s2 + xp2 + bias));
            asm("tanh.approx.f32 %0, %1;" : "=f"(t3) : "f"(s3 + xp3 + bias));
            const float4 hold = *reinterpret_cast<const float4*>(myhb + par * 2048 + gcu * 4);
            float4 v;
            v.x = 0.9f * hold.x + 0.1f * t0;
            v.y = 0.9f * hold.y + 0.1f * t1;
            v.z = 0.9f * hold.z + 0.1f * t2;
            v.w = 0.9f * hold.w + 0.1f * t3;

            // Push h(t) into slot (t+1)&1 at all 8 CTAs (incl. self).
            // ALSO at t=RT-1 (post-loop out[511]/h_final pass reads hb[0]).
            const uint32_t doff = grpoff + (uint32_t)((par ^ 1) * 8192) + choff;
#pragma unroll
            for (int r = 0; r < 8; r++)
                asm volatile("st.shared::cluster.v4.f32 [%0], {%1,%2,%3,%4};"
                             :: "r"(pb[r] + doff),
                                "f"(v.x), "f"(v.y), "f"(v.z), "f"(v.w) : "memory");
        } else if (t > 0) {
            // ---- upper: output GEMM for step t-1 (h(t-1) == hb[par]) ----
            // Transpose hb[par] k-major -> hbt b-major (conflict-free k map)
#pragma unroll
            for (int i = 0; i < 8; i++) {
                const int lin = i * 128 + ut;         // 0..1023
                const int g = lin >> 9, k = lin & 511;
                const float4 hv = *reinterpret_cast<const float4*>(
                    (g ? hb1 : hb0) + par * 2048 + k * 4);
                hbt[(g * 4 + 0) * K2_HBT_STR + k] = hv.x;
                hbt[(g * 4 + 1) * K2_HBT_STR + k] = hv.y;
                hbt[(g * 4 + 2) * K2_HBT_STR + k] = hv.z;
                hbt[(g * 4 + 3) * K2_HBT_STR + k] = hv.w;
            }
            asm volatile("bar.sync 1, 128;" ::: "memory");

            // Dot: sum over k in [ukh*256, ukh*256+256)
            const float* wrow = Wo + uo * K2_WO_STR + ukh * 256;
            const float* hrow = hbt + ub8 * K2_HBT_STR + ukh * 256;
            uint64_t accp = 0;
#pragma unroll 8
            for (int k4 = 0; k4 < 64; k4++) {
                const ulonglong2 wv = *reinterpret_cast<const ulonglong2*>(wrow + k4 * 4);
                const ulonglong2 hv = *reinterpret_cast<const ulonglong2*>(hrow + k4 * 4);
                FMA2(accp, wv.x, hv.x);
                FMA2(accp, wv.y, hv.y);
            }
            float alo, ahi;
            UPK2(alo, ahi, accp);
            float s = alo + ahi;
            s += __shfl_xor_sync(0xFFFFFFFF, s, 8);
            if (ukh == 0)
                out_p[(size_t)(t - 1) * RO] = s + ubo;
        }

        // ---- cluster barrier (arrive / hidden work / wait) ----
        asm volatile("barrier.cluster.arrive.aligned;" ::: "memory");
        if (tid < 128 && t + 1 < RT) {
            const size_t o2 = (size_t)(t + 1) * RH;
            xp0 = __ldg(xp_p + o2);
            xp1 = __ldg(xp_p + (size_t)RT * RH + o2);
            xp2 = __ldg(xp_p + 2 * (size_t)RT * RH + o2);
            xp3 = __ldg(xp_p + 3 * (size_t)RT * RH + o2);
        }
        asm volatile("barrier.cluster.wait.aligned;" ::: "memory");
    }

    // ---- post-loop: out[511] from h(511) (in hb[0]); then h_final ----
    if (tid >= 128) {
#pragma unroll
        for (int i = 0; i < 8; i++) {
            const int lin = i * 128 + ut;
            const int g = lin >> 9, k = lin & 511;
            const float4 hv = *reinterpret_cast<const float4*>(
                (g ? hb1 : hb0) + k * 4);             // parity-0 slot
            hbt[(g * 4 + 0) * K2_HBT_STR + k] = hv.x;
            hbt[(g * 4 + 1) * K2_HBT_STR + k] = hv.y;
            hbt[(g * 4 + 2) * K2_HBT_STR + k] = hv.z;
            hbt[(g * 4 + 3) * K2_HBT_STR + k] = hv.w;
        }
        asm volatile("bar.sync 1, 128;" ::: "memory");
        const float* wrow = Wo + uo * K2_WO_STR + ukh * 256;
        const float* hrow = hbt + ub8 * K2_HBT_STR + ukh * 256;
        uint64_t accp = 0;
#pragma unroll 8
        for (int k4 = 0; k4 < 64; k4++) {
            const ulonglong2 wv = *reinterpret_cast<const ulonglong2*>(wrow + k4 * 4);
            const ulonglong2 hv = *reinterpret_cast<const ulonglong2*>(hrow + k4 * 4);
            FMA2(accp, wv.x, hv.x);
            FMA2(accp, wv.y, hv.y);
        }
        float alo, ahi;
        UPK2(alo, ahi, accp);
        float s = alo + ahi;
        s += __shfl_xor_sync(0xFFFFFFFF, s, 8);
        if (ukh == 0)
            out_p[(size_t)(RT - 1) * RO] = s + ubo;
    }
    __syncthreads();
    // h_final: out + B*T*O region, [B][H]; each cluster writes its 8 rows
    {
        float* outh = out + (size_t)RB * RT * RO;
        for (int idx = tid; idx < 4096; idx += 256) {
            const int b8 = idx >> 9, k = idx & 511;
            const int g = b8 >> 2, b = b8 & 3;
            outh[(size_t)(b0 + b8) * RH + k] = (g ? hb1 : hb0)[k * 4 + b];
        }
    }
}

// ---------------------------------------------------------------------------
// Launch
// ---------------------------------------------------------------------------
extern "C" void kernel_launch(void* const* d_in, const int* in_sizes, int n_in,
                              void* d_out, int out_size) {
    const float* inputs = (const float*)d_in[0];
    const float* hidden = (const float*)d_in[1];
    const float* W_in   = (const float*)d_in[2];
    const float* W_rec  = (const float*)d_in[3];
    const float* bvec   = (const float*)d_in[4];
    const float* W_out  = (const float*)d_in[5];
    const float* b_out  = (const float*)d_in[6];
    float* out = (float*)d_out;

    cudaFuncSetAttribute(k1_xproj, cudaFuncAttributeMaxDynamicSharedMemorySize, K1_SMEM_BYTES);
    cudaFuncSetAttribute(k2_rnn,   cudaFuncAttributeMaxDynamicSharedMemorySize, K2_SMEM_BYTES);

    k0_transpose<<<(RI * RH) / 256, 256>>>(W_in);
    k1_xproj<<<dim3((RB * RT) / 64, RH / 128), 256, K1_SMEM_BYTES>>>(inputs);

    cudaLaunchConfig_t cfg = {};
    cfg.gridDim  = dim3(64, 1, 1);            // 8 clusters x 8 CTAs
    cfg.blockDim = dim3(256, 1, 1);
    cfg.dynamicSmemBytes = K2_SMEM_BYTES;
    cfg.stream = 0;
    cudaLaunchAttribute attrs[1];
    attrs[0].id = cudaLaunchAttributeClusterDimension;
    attrs[0].val.clusterDim.x = 8;
    attrs[0].val.clusterDim.y = 1;
    attrs[0].val.clusterDim.z = 1;
    cfg.attrs = attrs;
    cfg.numAttrs = 1;
    cudaLaunchKernelEx(&cfg, k2_rnn, hidden, W_rec, bvec, W_out, b_out, out);
}